// round 11
// baseline (speedup 1.0000x reference)
#include <cuda_runtime.h>
#include <cuda_bf16.h>
#include <cstdint>

// Problem constants
#define B_SZ   16
#define CIN    512
#define L_IN   4000
#define KW     16
#define L_OUT  31992            // 3999*8
#define CSPLIT 2
#define CHALF  (CIN / CSPLIT)   // 256
#define MP     2                // m-values per thread
#define TPB    128              // threads per zgemm block
#define TILE_M (TPB * MP)       // 256 columns per block
#define NTILES ((L_IN + TILE_M - 1) / TILE_M)   // 16

// Split-z scratch, pre-shifted for elementwise combine:
//   zA [half][b][m][p] = z[half][b][m  ][p+8]
//   zBs[half][b][m][p] = z[half][b][m+1][p  ]
// y[b][8m+p] = sum_half( zA + zBs ).
__device__ float g_zA [CSPLIT * B_SZ * L_IN * 8];   // 4.1 MB
__device__ float g_zBs[CSPLIT * B_SZ * L_IN * 8];   // 4.1 MB

// ---------------------------------------------------------------------------
// Kernel 1: per-sample skinny GEMM, f32x2 packed over K-PAIRS.
// Grid: (16 m-tiles of 256 cols, 16 batch, 2 cin-halves) = 512 blocks x 128thr
// -> single wave at 3-4 blocks/SM, 12-16 warps/SM, MLP-8 -> HBM-saturating.
// ---------------------------------------------------------------------------
extern "C" __global__ void __launch_bounds__(TPB)
zgemm_kernel(const float* __restrict__ x,
             const float* __restrict__ t60s,
             const float* __restrict__ kw)
{
    __shared__ __align__(16) float Wsm[CHALF * KW];   // natural layout, 16 KB

    const int b    = blockIdx.y;
    const int half = blockIdx.z;
    const int idxb = (int)rintf(t60s[b & 7] * 100.0f) - 10;
    const float4* wsrc = (const float4*)(kw + (size_t)idxb * (CIN * KW)
                                            + half * (CHALF * KW));
    float4* wdst = (float4*)Wsm;
#pragma unroll
    for (int i = threadIdx.x; i < CHALF * KW / 4; i += TPB)
        wdst[i] = wsrc[i];
    __syncthreads();

    const int m = blockIdx.x * TILE_M + threadIdx.x * MP;
    if (m >= L_IN) return;   // partial last tile (after the only __syncthreads)

    const float* xp = x + (size_t)b * CIN * L_IN + (size_t)half * CHALF * L_IN + m;
    const ulonglong2* Wp = (const ulonglong2*)Wsm;

    unsigned long long acc[MP][8];                    // [m][k-pair] {k_lo,k_hi}
#pragma unroll
    for (int mi = 0; mi < MP; ++mi)
#pragma unroll
        for (int j = 0; j < 8; ++j) acc[mi][j] = 0ULL;

#pragma unroll 8
    for (int cin = 0; cin < CHALF; ++cin) {
        float2 xq = *(const float2*)(xp + (size_t)cin * L_IN);   // m, m+1
        unsigned long long xv[MP];
        asm("mov.b64 %0, {%1, %1};" : "=l"(xv[0]) : "f"(xq.x));
        asm("mov.b64 %0, {%1, %1};" : "=l"(xv[1]) : "f"(xq.y));

        ulonglong2 wA = Wp[cin * 4 + 0];   // warp-uniform -> broadcast LDS
        ulonglong2 wB = Wp[cin * 4 + 1];
        ulonglong2 wC = Wp[cin * 4 + 2];
        ulonglong2 wD = Wp[cin * 4 + 3];
#pragma unroll
        for (int mi = 0; mi < MP; ++mi) {
            asm("fma.rn.f32x2 %0, %1, %2, %0;" : "+l"(acc[mi][0]) : "l"(xv[mi]), "l"(wA.x));
            asm("fma.rn.f32x2 %0, %1, %2, %0;" : "+l"(acc[mi][1]) : "l"(xv[mi]), "l"(wA.y));
            asm("fma.rn.f32x2 %0, %1, %2, %0;" : "+l"(acc[mi][2]) : "l"(xv[mi]), "l"(wB.x));
            asm("fma.rn.f32x2 %0, %1, %2, %0;" : "+l"(acc[mi][3]) : "l"(xv[mi]), "l"(wB.y));
            asm("fma.rn.f32x2 %0, %1, %2, %0;" : "+l"(acc[mi][4]) : "l"(xv[mi]), "l"(wC.x));
            asm("fma.rn.f32x2 %0, %1, %2, %0;" : "+l"(acc[mi][5]) : "l"(xv[mi]), "l"(wC.y));
            asm("fma.rn.f32x2 %0, %1, %2, %0;" : "+l"(acc[mi][6]) : "l"(xv[mi]), "l"(wD.x));
            asm("fma.rn.f32x2 %0, %1, %2, %0;" : "+l"(acc[mi][7]) : "l"(xv[mi]), "l"(wD.y));
        }
    }

    // Store split-z: back half -> zA[m], front half -> zBs[m-1] (shifted).
    const size_t colbase = (((size_t)half * B_SZ + b) * L_IN + m) * 8;
    float* zA  = g_zA  + colbase;
    float* zBs = g_zBs + colbase - 8;      // column m-1 slot (guarded for m==0)
#pragma unroll
    for (int mi = 0; mi < MP; ++mi) {
        float f[KW];
#pragma unroll
        for (int j = 0; j < 8; ++j)
            asm("mov.b64 {%0, %1}, %2;" : "=f"(f[2*j]), "=f"(f[2*j+1]) : "l"(acc[mi][j]));

        ((float4*)(zA + mi * 8))[0] = make_float4(f[ 8], f[ 9], f[10], f[11]);
        ((float4*)(zA + mi * 8))[1] = make_float4(f[12], f[13], f[14], f[15]);
        if (m + mi > 0) {
            ((float4*)(zBs + mi * 8))[0] = make_float4(f[0], f[1], f[2], f[3]);
            ((float4*)(zBs + mi * 8))[1] = make_float4(f[4], f[5], f[6], f[7]);
        }
    }
}

// ---------------------------------------------------------------------------
// Kernel 2: elementwise float4 add; 2 float4 per array per thread (MLP 8):
//   out4[b][i] = zA0[i] + zBs0[i] + zA1[i] + zBs1[i]
// ---------------------------------------------------------------------------
extern "C" __global__ void __launch_bounds__(256)
combine_kernel(float* __restrict__ out)
{
    const int i0 = (blockIdx.x * 256 + threadIdx.x) * 2;
    const int b  = blockIdx.y;
    if (i0 >= (L_OUT / 4)) return;                     // 7998 float4 per sample

    const float4* zA0 = (const float4*)g_zA  + (size_t)b * L_IN * 2;
    const float4* zB0 = (const float4*)g_zBs + (size_t)b * L_IN * 2;
    const float4* zA1 = (const float4*)g_zA  + ((size_t)B_SZ + b) * L_IN * 2;
    const float4* zB1 = (const float4*)g_zBs + ((size_t)B_SZ + b) * L_IN * 2;
    float4* op = (float4*)(out + (size_t)b * L_OUT);

    float4 a0 = zA0[i0],     p0 = zB0[i0],     c0 = zA1[i0],     q0 = zB1[i0];
    float4 a1 = zA0[i0 + 1], p1 = zB0[i0 + 1], c1 = zA1[i0 + 1], q1 = zB1[i0 + 1];

    op[i0] = make_float4((a0.x + p0.x) + (c0.x + q0.x),
                         (a0.y + p0.y) + (c0.y + q0.y),
                         (a0.z + p0.z) + (c0.z + q0.z),
                         (a0.w + p0.w) + (c0.w + q0.w));
    op[i0 + 1] = make_float4((a1.x + p1.x) + (c1.x + q1.x),
                             (a1.y + p1.y) + (c1.y + q1.y),
                             (a1.z + p1.z) + (c1.z + q1.z),
                             (a1.w + p1.w) + (c1.w + q1.w));
}

// ---------------------------------------------------------------------------
extern "C" void kernel_launch(void* const* d_in, const int* in_sizes, int n_in,
                              void* d_out, int out_size)
{
    const float* x    = (const float*)d_in[0];   // (16, 512, 4000) f32
    const float* t60s = (const float*)d_in[1];   // (8,)            f32
    const float* kw   = (const float*)d_in[2];   // (41, 512, 1, 16) f32
    float*       out  = (float*)d_out;           // (16, 1, 31992)  f32

    dim3 g1(NTILES, B_SZ, CSPLIT);   // 16 x 16 x 2 = 512 blocks, 128 thr
    zgemm_kernel<<<g1, TPB>>>(x, t60s, kw);

    dim3 g2((L_OUT / 8 + 255) / 256, B_SZ);      // 3999 float4-pairs per sample
    combine_kernel<<<g2, 256>>>(out);
}

// round 12
// speedup vs baseline: 1.5180x; 1.5180x over previous
#include <cuda_runtime.h>
#include <cuda_bf16.h>
#include <cstdint>

// Problem constants
#define B_SZ   16
#define CIN    512
#define L_IN   4000
#define KW     16
#define L_OUT  31992            // 3999*8
#define CSPLIT 2
#define CHALF  (CIN / CSPLIT)   // 256
#define MP     2                // m-values per thread

// Split-z scratch, pre-shifted for elementwise combine:
//   zA [half][b][m][p] = z[half][b][m  ][p+8]
//   zBs[half][b][m][p] = z[half][b][m+1][p  ]
// y[b][8m+p] = sum_half( zA + zBs ).
__device__ float g_zA [CSPLIT * B_SZ * L_IN * 8];   // 4.1 MB
__device__ float g_zBs[CSPLIT * B_SZ * L_IN * 8];   // 4.1 MB

// ---------------------------------------------------------------------------
// Kernel 1 (R7 shape, proven): per-sample skinny GEMM, f32x2 over K-PAIRS.
// Grid: (8 m-tiles of 512, 16 batch, 2 halves) = 256 blocks x 256 thr,
// launch_bounds(256,2). NEW: explicit 8-deep load batching -- phase A issues
// 8 independent LDG.64 into a register array before phase B consumes any,
// guaranteeing MLP=8 (2 KB in flight per warp -> ~4.3 MB chip-wide).
// ---------------------------------------------------------------------------
extern "C" __global__ void __launch_bounds__(256, 2)
zgemm_kernel(const float* __restrict__ x,
             const float* __restrict__ t60s,
             const float* __restrict__ kw)
{
    __shared__ __align__(16) float Wsm[CHALF * KW];   // natural layout, 16 KB

    const int b    = blockIdx.y;
    const int half = blockIdx.z;
    const int idxb = (int)rintf(t60s[b & 7] * 100.0f) - 10;
    const float4* wsrc = (const float4*)(kw + (size_t)idxb * (CIN * KW)
                                            + half * (CHALF * KW));
    float4* wdst = (float4*)Wsm;
    for (int i = threadIdx.x; i < CHALF * KW / 4; i += 256)
        wdst[i] = wsrc[i];
    __syncthreads();

    const int m = blockIdx.x * (256 * MP) + threadIdx.x * MP;
    if (m >= L_IN) return;   // guard after the only __syncthreads

    const float* xp = x + (size_t)b * CIN * L_IN + (size_t)half * CHALF * L_IN + m;
    const ulonglong2* Wp = (const ulonglong2*)Wsm;

    unsigned long long acc[MP][8];                    // [m][k-pair]
#pragma unroll
    for (int mi = 0; mi < MP; ++mi)
#pragma unroll
        for (int j = 0; j < 8; ++j) acc[mi][j] = 0ULL;

#pragma unroll 1
    for (int cb = 0; cb < CHALF; cb += 8) {
        // Phase A: batch 8 independent LDG.64 (no consumers yet -> MLP=8)
        float2 xq[8];
#pragma unroll
        for (int j = 0; j < 8; ++j)
            xq[j] = *(const float2*)(xp + (size_t)(cb + j) * L_IN);

        // Phase B: consume
#pragma unroll
        for (int j = 0; j < 8; ++j) {
            const int cin = cb + j;
            unsigned long long xv0, xv1;
            asm("mov.b64 %0, {%1, %1};" : "=l"(xv0) : "f"(xq[j].x));
            asm("mov.b64 %0, {%1, %1};" : "=l"(xv1) : "f"(xq[j].y));

            ulonglong2 wA = Wp[cin * 4 + 0];   // warp-uniform -> broadcast LDS
            ulonglong2 wB = Wp[cin * 4 + 1];
            ulonglong2 wC = Wp[cin * 4 + 2];
            ulonglong2 wD = Wp[cin * 4 + 3];

            asm("fma.rn.f32x2 %0, %1, %2, %0;" : "+l"(acc[0][0]) : "l"(xv0), "l"(wA.x));
            asm("fma.rn.f32x2 %0, %1, %2, %0;" : "+l"(acc[0][1]) : "l"(xv0), "l"(wA.y));
            asm("fma.rn.f32x2 %0, %1, %2, %0;" : "+l"(acc[0][2]) : "l"(xv0), "l"(wB.x));
            asm("fma.rn.f32x2 %0, %1, %2, %0;" : "+l"(acc[0][3]) : "l"(xv0), "l"(wB.y));
            asm("fma.rn.f32x2 %0, %1, %2, %0;" : "+l"(acc[0][4]) : "l"(xv0), "l"(wC.x));
            asm("fma.rn.f32x2 %0, %1, %2, %0;" : "+l"(acc[0][5]) : "l"(xv0), "l"(wC.y));
            asm("fma.rn.f32x2 %0, %1, %2, %0;" : "+l"(acc[0][6]) : "l"(xv0), "l"(wD.x));
            asm("fma.rn.f32x2 %0, %1, %2, %0;" : "+l"(acc[0][7]) : "l"(xv0), "l"(wD.y));
            asm("fma.rn.f32x2 %0, %1, %2, %0;" : "+l"(acc[1][0]) : "l"(xv1), "l"(wA.x));
            asm("fma.rn.f32x2 %0, %1, %2, %0;" : "+l"(acc[1][1]) : "l"(xv1), "l"(wA.y));
            asm("fma.rn.f32x2 %0, %1, %2, %0;" : "+l"(acc[1][2]) : "l"(xv1), "l"(wB.x));
            asm("fma.rn.f32x2 %0, %1, %2, %0;" : "+l"(acc[1][3]) : "l"(xv1), "l"(wB.y));
            asm("fma.rn.f32x2 %0, %1, %2, %0;" : "+l"(acc[1][4]) : "l"(xv1), "l"(wC.x));
            asm("fma.rn.f32x2 %0, %1, %2, %0;" : "+l"(acc[1][5]) : "l"(xv1), "l"(wC.y));
            asm("fma.rn.f32x2 %0, %1, %2, %0;" : "+l"(acc[1][6]) : "l"(xv1), "l"(wD.x));
            asm("fma.rn.f32x2 %0, %1, %2, %0;" : "+l"(acc[1][7]) : "l"(xv1), "l"(wD.y));
        }
    }

    // Store split-z: back half -> zA[m], front half -> zBs[m-1] (shifted).
    const size_t colbase = (((size_t)half * B_SZ + b) * L_IN + m) * 8;
    float* zA  = g_zA  + colbase;
    float* zBs = g_zBs + colbase - 8;
#pragma unroll
    for (int mi = 0; mi < MP; ++mi) {
        float f[KW];
#pragma unroll
        for (int j = 0; j < 8; ++j)
            asm("mov.b64 {%0, %1}, %2;" : "=f"(f[2*j]), "=f"(f[2*j+1]) : "l"(acc[mi][j]));

        ((float4*)(zA + mi * 8))[0] = make_float4(f[ 8], f[ 9], f[10], f[11]);
        ((float4*)(zA + mi * 8))[1] = make_float4(f[12], f[13], f[14], f[15]);
        if (m + mi > 0) {
            ((float4*)(zBs + mi * 8))[0] = make_float4(f[0], f[1], f[2], f[3]);
            ((float4*)(zBs + mi * 8))[1] = make_float4(f[4], f[5], f[6], f[7]);
        }
    }
}

// ---------------------------------------------------------------------------
// Kernel 2: elementwise add, 4 float4 per array per thread = 16 independent
// LDG.128 in flight. Loads are UNGUARDED (per-sample z regions are 8000
// float4, max read index 7999 -> in bounds); only the out store is guarded.
// ---------------------------------------------------------------------------
extern "C" __global__ void __launch_bounds__(256)
combine_kernel(float* __restrict__ out)
{
    const int i0 = (blockIdx.x * 256 + threadIdx.x) * 4;
    const int b  = blockIdx.y;
    if (i0 >= (L_OUT / 4) + 2) return;                 // threads fully past region

    const float4* zA0 = (const float4*)g_zA  + (size_t)b * L_IN * 2;
    const float4* zB0 = (const float4*)g_zBs + (size_t)b * L_IN * 2;
    const float4* zA1 = (const float4*)g_zA  + ((size_t)B_SZ + b) * L_IN * 2;
    const float4* zB1 = (const float4*)g_zBs + ((size_t)B_SZ + b) * L_IN * 2;
    float4* op = (float4*)(out + (size_t)b * L_OUT);

    float4 a[4], p[4], c[4], q[4];
#pragma unroll
    for (int k = 0; k < 4; ++k) a[k] = zA0[i0 + k];
#pragma unroll
    for (int k = 0; k < 4; ++k) p[k] = zB0[i0 + k];
#pragma unroll
    for (int k = 0; k < 4; ++k) c[k] = zA1[i0 + k];
#pragma unroll
    for (int k = 0; k < 4; ++k) q[k] = zB1[i0 + k];

#pragma unroll
    for (int k = 0; k < 4; ++k) {
        if (i0 + k < (L_OUT / 4)) {
            op[i0 + k] = make_float4((a[k].x + p[k].x) + (c[k].x + q[k].x),
                                     (a[k].y + p[k].y) + (c[k].y + q[k].y),
                                     (a[k].z + p[k].z) + (c[k].z + q[k].z),
                                     (a[k].w + p[k].w) + (c[k].w + q[k].w));
        }
    }
}

// ---------------------------------------------------------------------------
extern "C" void kernel_launch(void* const* d_in, const int* in_sizes, int n_in,
                              void* d_out, int out_size)
{
    const float* x    = (const float*)d_in[0];   // (16, 512, 4000) f32
    const float* t60s = (const float*)d_in[1];   // (8,)            f32
    const float* kw   = (const float*)d_in[2];   // (41, 512, 1, 16) f32
    float*       out  = (float*)d_out;           // (16, 1, 31992)  f32

    dim3 g1(8, B_SZ, CSPLIT);    // 8 m-tiles of 512 cols, 16 samples, 2 halves
    zgemm_kernel<<<g1, 256>>>(x, t60s, kw);

    // 2000 threads per sample (4 float4 each covers 8000 >= 7998)
    dim3 g2((2000 + 255) / 256, B_SZ);
    combine_kernel<<<g2, 256>>>(out);
}